// round 1
// baseline (speedup 1.0000x reference)
#include <cuda_runtime.h>
#include <cuda_bf16.h>
#include <cstdint>

// Problem constants
#define Hn 1024
#define Bn 128
#define Tn 400
#define Sn 64
#define Cn 8
#define NOUTn 3
#define NCLSn 3
#define BOTn 2
#define CLSOUTn 8
#define NEXC 819              // int(1024 * 0.8)

#define NCTA 128              // CTAs in scan kernel (one j-slice each)
#define JPC 8                 // hidden columns per CTA (128 * 8 = 1024)

#define ALPHA_N 0.2f          // DT/TAU_N = 20/100
#define DT_SEC 0.02f
#define NOISE_STD 0.05f
#define AX_SLOW ((float)(20.0 / 1500.0))
#define AX_FAST ((float)(20.0 / 200.0))

#define NR (NOUTn + NCLSn * CLSOUTn)   // 27 fused readout rows

// ---------------- device scratch (no cudaMalloc allowed) ----------------
__device__ float g_drive[(size_t)Tn * Bn * Hn];   // [t][b][h]  (~210 MB)
__device__ float g_hpT[2][Hn * Bn];               // transposed h_post, double buffered
__device__ float g_winT[Sn * Hn];                 // w_in transposed [s][h]
__device__ float g_wctxT[Cn * Hn];                // w_ctx transposed [c][h]
__device__ float g_comb[NR * Hn];                 // fused readout weights (w_out + c2@c1)
__device__ float g_combb[NR];                     // fused biases
__device__ unsigned g_count;                      // barrier arrival counter
__device__ volatile unsigned g_phase;             // barrier phase

// ---------------- prep: reset barrier, transpose weights, fuse classifiers ----
__global__ void prep_kernel(const float* __restrict__ w_in,
                            const float* __restrict__ w_ctx,
                            const float* __restrict__ w_out,
                            const float* __restrict__ b_out,
                            const float* __restrict__ c1_w,
                            const float* __restrict__ c1_b,
                            const float* __restrict__ c2_w,
                            const float* __restrict__ c2_b) {
    int idx = blockIdx.x * blockDim.x + threadIdx.x;
    if (idx == 0) { g_count = 0; g_phase = 0; }

    if (idx < Hn * Sn) {                      // transpose w_in [H,S] -> [S,H]
        int h = idx / Sn, s = idx % Sn;
        g_winT[s * Hn + h] = w_in[idx];
    }
    if (idx < Hn * Cn) {                      // transpose w_ctx [H,C] -> [C,H]
        int h = idx / Cn, c = idx % Cn;
        g_wctxT[c * Hn + h] = w_ctx[idx];
    }
    if (idx < NOUTn * Hn) {                   // rows 0..2 : w_out
        g_comb[idx] = w_out[idx];
    }
    if (idx < NCLSn * CLSOUTn * Hn) {         // rows 3..26 : c2_w @ c1_w
        int r = idx / Hn, h = idx % Hn;
        int j = r / CLSOUTn, o = r % CLSOUTn;
        float acc = 0.f;
        #pragma unroll
        for (int k = 0; k < BOTn; k++)
            acc += c2_w[(j * CLSOUTn + o) * BOTn + k] * c1_w[(j * BOTn + k) * Hn + h];
        g_comb[(NOUTn + r) * Hn + h] = acc;
    }
    if (idx < NOUTn) g_combb[idx] = b_out[idx];
    if (idx >= NOUTn && idx < NR) {
        int r = idx - NOUTn;
        int j = r / CLSOUTn, o = r % CLSOUTn;
        float acc = c2_b[j * CLSOUTn + o];
        #pragma unroll
        for (int k = 0; k < BOTn; k++)
            acc += c2_w[(j * CLSOUTn + o) * BOTn + k] * c1_b[j * BOTn + k];
        g_combb[idx] = acc;
    }
}

// ---------------- drive: [t][b][h] = stim@w_in^T + ctx@w_ctx^T ----------------
#define DG 8   // (t,b) pairs per block
__global__ void drive_kernel(const float* __restrict__ stim,
                             const float* __restrict__ ctx) {
    __shared__ float s_in[DG][Sn + Cn];
    int p0 = blockIdx.x * DG;                         // pair index p = t*B + b
    int h = blockIdx.y * blockDim.x + threadIdx.x;

    for (int i = threadIdx.x; i < DG * (Sn + Cn); i += blockDim.x) {
        int g = i / (Sn + Cn), q = i % (Sn + Cn);
        int p = p0 + g;
        int t = p / Bn, b = p % Bn;
        float v;
        if (q < Sn) v = stim[((size_t)b * Tn + t) * Sn + q];
        else        v = ctx[((size_t)b * Tn + t) * Cn + (q - Sn)];
        s_in[g][q] = v;
    }
    __syncthreads();

    float acc[DG];
    #pragma unroll
    for (int g = 0; g < DG; g++) acc[g] = 0.f;

    #pragma unroll 8
    for (int s = 0; s < Sn; s++) {
        float w = g_winT[s * Hn + h];
        #pragma unroll
        for (int g = 0; g < DG; g++) acc[g] = fmaf(s_in[g][s], w, acc[g]);
    }
    #pragma unroll
    for (int c = 0; c < Cn; c++) {
        float w = g_wctxT[c * Hn + h];
        #pragma unroll
        for (int g = 0; g < DG; g++) acc[g] = fmaf(s_in[g][Sn + c], w, acc[g]);
    }
    #pragma unroll
    for (int g = 0; g < DG; g++)
        g_drive[(size_t)(p0 + g) * Hn + h] = acc[g];
}

// ---------------- persistent scan kernel ----------------
__global__ void __launch_bounds__(Bn, 1) scan_kernel(
        const float* __restrict__ w_rec,
        const float* __restrict__ b_rec,
        const float* __restrict__ noise,
        float* __restrict__ acts) {
    __shared__ float w_sm[Hn * JPC];   // W_eff[k][jj] for this CTA's j-slice (32 KB)
    const int c = blockIdx.x;
    const int b = threadIdx.x;         // one batch row per thread
    const int j0 = c * JPC;

    // Build effective recurrent weights for owned columns: sign * relu * no-diag
    for (int idx = b; idx < Hn * JPC; idx += Bn) {
        int k = idx / JPC, jj = idx % JPC;
        int j = j0 + jj;
        float w = fmaxf(w_rec[(size_t)k * Hn + j], 0.f);
        if (k == j) w = 0.f;
        w_sm[idx] = (k < NEXC) ? w : -w;
    }
    float br[JPC];
    #pragma unroll
    for (int jj = 0; jj < JPC; jj++) br[jj] = b_rec[j0 + jj];
    __syncthreads();

    // State in registers
    float h[JPC], sx[JPC], su[JPC], Uv[JPC], ax[JPC];
    #pragma unroll
    for (int jj = 0; jj < JPC; jj++) {
        int j = j0 + jj;
        bool odd = (j & 1);
        ax[jj] = odd ? AX_FAST : AX_SLOW;
        Uv[jj] = odd ? 0.15f : 0.45f;
        h[jj] = 0.f;
        sx[jj] = 1.f;
        su[jj] = Uv[jj];
    }

    for (int step = 0; step < Tn; step++) {
        float* hpT = g_hpT[step & 1];

        // ---- STP update + write transposed h_post ----
        #pragma unroll
        for (int jj = 0; jj < JPC; jj++) {
            float hh = h[jj];
            float sxo = sx[jj], suo = su[jj];
            float sxn = sxo + ax[jj] * (1.f - sxo) - DT_SEC * suo * sxo * hh;
            float sun = suo + ax[jj] * (Uv[jj] - suo) + DT_SEC * Uv[jj] * (1.f - suo) * hh;
            sxn = fminf(fmaxf(sxn, 0.f), 1.f);
            sun = fminf(fmaxf(sun, 0.f), 1.f);
            sx[jj] = sxn;
            su[jj] = sun;
            hpT[(j0 + jj) * Bn + b] = sun * sxn * hh;
        }

        // ---- grid barrier (monotonic phase, one per step) ----
        __threadfence();
        __syncthreads();
        if (b == 0) {
            unsigned target = (unsigned)(step + 1);
            unsigned v = atomicAdd(&g_count, 1u);
            if (v == target * NCTA - 1u) {
                __threadfence();
                g_phase = target;
            } else {
                while (g_phase < target) { }
            }
            __threadfence();
        }
        __syncthreads();

        // ---- GEMM: acc[jj] = sum_k hpT[k][b] * W[k][j0+jj] ----
        float acc[JPC];
        #pragma unroll
        for (int jj = 0; jj < JPC; jj++) acc[jj] = 0.f;

        const float* __restrict__ hpcol = hpT + b;
        float hvA[32], hvB[32];
        #pragma unroll
        for (int u = 0; u < 32; u++) hvA[u] = hpcol[u * Bn];

        for (int kb = 0; kb < Hn; kb += 64) {
            // prefetch second half of this 64-block
            #pragma unroll
            for (int u = 0; u < 32; u++) hvB[u] = hpcol[(kb + 32 + u) * Bn];
            // compute first half
            #pragma unroll
            for (int u = 0; u < 32; u++) {
                const float* wr = &w_sm[(kb + u) * JPC];
                #pragma unroll
                for (int jj = 0; jj < JPC; jj++)
                    acc[jj] = fmaf(hvA[u], wr[jj], acc[jj]);
            }
            // prefetch first half of next 64-block
            if (kb + 64 < Hn) {
                #pragma unroll
                for (int u = 0; u < 32; u++) hvA[u] = hpcol[(kb + 64 + u) * Bn];
            }
            // compute second half
            #pragma unroll
            for (int u = 0; u < 32; u++) {
                const float* wr = &w_sm[(kb + 32 + u) * JPC];
                #pragma unroll
                for (int jj = 0; jj < JPC; jj++)
                    acc[jj] = fmaf(hvB[u], wr[jj], acc[jj]);
            }
        }

        // ---- h update + write acts ----
        const size_t off = ((size_t)step * Bn + b) * Hn + j0;
        const float* __restrict__ drv = g_drive + off;
        const float* __restrict__ nz  = noise + off;
        float* __restrict__ ao = acts + ((size_t)b * Tn + step) * Hn + j0;
        #pragma unroll
        for (int jj = 0; jj < JPC; jj++) {
            float val = h[jj] * (1.f - ALPHA_N)
                      + ALPHA_N * (drv[jj] + acc[jj] + br[jj])
                      + NOISE_STD * nz[jj];
            float hn = fmaxf(val, 0.f);
            h[jj] = hn;
            ao[jj] = hn;
        }
    }
}

// ---------------- post: fused readout (outputs + classifier logits) ----------------
__global__ void post_kernel(const float* __restrict__ acts,
                            float* __restrict__ out0,
                            float* __restrict__ pout) {
    __shared__ float s_a[Hn];
    __shared__ float s_red[8][NR];
    int bt = blockIdx.x;                     // bt = b*T + t
    const float* arow = acts + (size_t)bt * Hn;
    int tid = threadIdx.x;                   // 256 threads

    for (int i = tid; i < Hn; i += 256) s_a[i] = arow[i];
    __syncthreads();

    float part[NR];
    #pragma unroll
    for (int r = 0; r < NR; r++) part[r] = 0.f;

    for (int i = tid; i < Hn; i += 256) {
        float a = s_a[i];
        #pragma unroll
        for (int r = 0; r < NR; r++)
            part[r] = fmaf(a, g_comb[r * Hn + i], part[r]);
    }
    #pragma unroll
    for (int r = 0; r < NR; r++) {
        #pragma unroll
        for (int off = 16; off > 0; off >>= 1)
            part[r] += __shfl_down_sync(0xffffffffu, part[r], off);
    }
    int wid = tid >> 5, lid = tid & 31;
    if (lid == 0) {
        #pragma unroll
        for (int r = 0; r < NR; r++) s_red[wid][r] = part[r];
    }
    __syncthreads();
    if (tid < NR) {
        float s = 0.f;
        #pragma unroll
        for (int w = 0; w < 8; w++) s += s_red[w][tid];
        s += g_combb[tid];
        if (tid < NOUTn) out0[(size_t)bt * NOUTn + tid] = s;
        else             pout[(size_t)bt * (NCLSn * CLSOUTn) + (tid - NOUTn)] = s;
    }
}

// ---------------- launch ----------------
extern "C" void kernel_launch(void* const* d_in, const int* in_sizes, int n_in,
                              void* d_out, int out_size) {
    const float* stim  = (const float*)d_in[0];
    const float* ctx   = (const float*)d_in[1];
    const float* w_rec = (const float*)d_in[2];
    const float* b_rec = (const float*)d_in[3];
    const float* w_in  = (const float*)d_in[4];
    const float* w_ctx = (const float*)d_in[5];
    const float* w_out = (const float*)d_in[6];
    const float* b_out = (const float*)d_in[7];
    const float* c1_w  = (const float*)d_in[8];
    const float* c1_b  = (const float*)d_in[9];
    const float* c2_w  = (const float*)d_in[10];
    const float* c2_b  = (const float*)d_in[11];
    const float* noise = (const float*)d_in[12];

    float* out0 = (float*)d_out;                         // [B, T, 3]
    float* acts = out0 + (size_t)Bn * Tn * NOUTn;        // [B, T, H]
    float* pout = acts + (size_t)Bn * Tn * Hn;           // [B, T, 3, 8]

    prep_kernel<<<256, 256>>>(w_in, w_ctx, w_out, b_out, c1_w, c1_b, c2_w, c2_b);

    dim3 dgrid(Tn * Bn / DG, Hn / 256);
    drive_kernel<<<dgrid, 256>>>(stim, ctx);

    scan_kernel<<<NCTA, Bn>>>(w_rec, b_rec, noise, acts);

    post_kernel<<<Bn * Tn, 256>>>(acts, out0, pout);
}